// round 2
// baseline (speedup 1.0000x reference)
#include <cuda_runtime.h>

// Problem constants
#define BATCH   256
#define FEAT    1500
#define INSZ    28224
#define SPLITK  12          // encoder split-K: 12 * 2352 = 28224

// GEMM tiling
#define BM 128
#define BN 128
#define BK 16
#define TM 8
#define TN 8
#define NTHREADS 256        // (BM/TM)*(BN/TN)

typedef unsigned long long u64;

// Scratch (no allocations allowed -> device globals)
__device__ float g_preact[SPLITK * BATCH * FEAT];   // 18.4 MB
__device__ float g_yenc[BATCH * FEAT];              // 1.5 MB
__device__ float g_rownorm2[FEAT];

__device__ __forceinline__ float sigmoidf_(float z) {
    return 1.0f / (1.0f + __expf(-z));
}

__device__ __forceinline__ u64 pack2(float x, float y) {
    u64 r;
    asm("mov.b64 %0, {%1, %2};" : "=l"(r) : "f"(x), "f"(y));
    return r;
}
__device__ __forceinline__ void unpack2(u64 v, float& x, float& y) {
    asm("mov.b64 {%0, %1}, %2;" : "=f"(x), "=f"(y) : "l"(v));
}
__device__ __forceinline__ void fma2(u64& d, u64 a, u64 b) {
    // packed f32x2 FMA: 2 FMAs per issue slot (ptxas never emits this from C++)
    asm("fma.rn.f32x2 %0, %1, %2, %0;" : "+l"(d) : "l"(a), "l"(b));
}

// ---------------------------------------------------------------------------
// Kernel 1: row_norm2[f] = sum_i W_enc[f,i]^2 ; also zero-init jac accumulator
// ---------------------------------------------------------------------------
__global__ void rownorm_kernel(const float* __restrict__ W, float* __restrict__ jac_init) {
    int f = blockIdx.x;
    const float4* row = reinterpret_cast<const float4*>(W + (size_t)f * INSZ);
    float s = 0.f;
    for (int i = threadIdx.x; i < INSZ / 4; i += blockDim.x) {
        float4 v = row[i];
        s += v.x * v.x + v.y * v.y + v.z * v.z + v.w * v.w;
    }
    __shared__ float red[256];
    red[threadIdx.x] = s;
    __syncthreads();
    for (int o = 128; o > 0; o >>= 1) {
        if (threadIdx.x < o) red[threadIdx.x] += red[threadIdx.x + o];
        __syncthreads();
    }
    if (threadIdx.x == 0) g_rownorm2[f] = red[0];
    if (blockIdx.x == 0 && threadIdx.x == 0) *jac_init = 0.f;
}

// ---------------------------------------------------------------------------
// Kernel 2: tiled NT GEMM  C[m,n] = sum_k A[m,k]*B[n,k]   (both K-contiguous)
//   mode 0: write raw partial over K-slice z into C + z*M*N      (encoder)
//   mode 1: write sigmoid(acc + bias[n])                         (decoder)
// Inner loop uses packed fma.rn.f32x2 (2x FFMA issue rate on sm_103a).
// ---------------------------------------------------------------------------
__global__ void __launch_bounds__(NTHREADS, 2)
sgemm_nt(const float* __restrict__ A, const float* __restrict__ B,
         const float* __restrict__ bias, float* __restrict__ C,
         int M, int N, int K, int kChunk, int mode)
{
    __shared__ float As[BK][BM];
    __shared__ float Bs[BK][BN];

    const int tid = threadIdx.x;
    const int bm = blockIdx.y * BM;
    const int bn = blockIdx.x * BN;
    const int z  = blockIdx.z;
    const int kbeg = z * kChunk;
    const int kend = min(K, kbeg + kChunk);

    const int trow = tid / (BN / TN);  // 0..15
    const int tcol = tid % (BN / TN);  // 0..15

    // accumulators packed along N in f32x2 pairs
    u64 acc2[TM][TN / 2];
    #pragma unroll
    for (int i = 0; i < TM; i++)
        #pragma unroll
        for (int j = 0; j < TN / 2; j++) acc2[i][j] = 0ULL;

    const int lrow = tid / (BK / 4);        // 0..63
    const int lcol = (tid % (BK / 4)) * 4;  // 0,4,8,12

    for (int kt = kbeg; kt < kend; kt += BK) {
        // ---- load A tile (BM x BK), transpose into As[k][m] ----
        #pragma unroll
        for (int i = 0; i < 2; i++) {
            int r  = lrow + i * 64;
            int gm = bm + r;                 // always < M (M % BM == 0)
            int gk = kt + lcol;
            const float* p = A + (size_t)gm * K;
            float4 v = make_float4(0.f, 0.f, 0.f, 0.f);
            if (gk + 4 <= kend) {
                v = *reinterpret_cast<const float4*>(p + gk);
            } else {
                if (gk + 0 < kend) v.x = p[gk + 0];
                if (gk + 1 < kend) v.y = p[gk + 1];
                if (gk + 2 < kend) v.z = p[gk + 2];
                if (gk + 3 < kend) v.w = p[gk + 3];
            }
            As[lcol + 0][r] = v.x; As[lcol + 1][r] = v.y;
            As[lcol + 2][r] = v.z; As[lcol + 3][r] = v.w;
        }
        // ---- load B tile (BN x BK), transpose into Bs[k][n] ----
        #pragma unroll
        for (int i = 0; i < 2; i++) {
            int r  = lrow + i * 64;
            int gn = bn + r;
            int gk = kt + lcol;
            float4 v = make_float4(0.f, 0.f, 0.f, 0.f);
            if (gn < N) {
                const float* p = B + (size_t)gn * K;
                if (gk + 4 <= kend) {
                    v = *reinterpret_cast<const float4*>(p + gk);
                } else {
                    if (gk + 0 < kend) v.x = p[gk + 0];
                    if (gk + 1 < kend) v.y = p[gk + 1];
                    if (gk + 2 < kend) v.z = p[gk + 2];
                    if (gk + 3 < kend) v.w = p[gk + 3];
                }
            }
            Bs[lcol + 0][r] = v.x; Bs[lcol + 1][r] = v.y;
            Bs[lcol + 2][r] = v.z; Bs[lcol + 3][r] = v.w;
        }
        __syncthreads();

        // ---- compute: TM x TN outer product per thread, packed f32x2 ----
        #pragma unroll
        for (int k = 0; k < BK; k++) {
            u64 bf2[TN / 2];
            #pragma unroll
            for (int j = 0; j < TN / 2; j++)
                bf2[j] = *reinterpret_cast<const u64*>(&Bs[k][tcol * TN + 2 * j]);
            #pragma unroll
            for (int i = 0; i < TM; i++) {
                float a = As[k][trow * TM + i];
                u64 a2 = pack2(a, a);
                #pragma unroll
                for (int j = 0; j < TN / 2; j++)
                    fma2(acc2[i][j], a2, bf2[j]);
            }
        }
        __syncthreads();
    }

    // ---- epilogue ----
    if (mode == 0) {
        float* Cz = C + (size_t)z * M * N;
        #pragma unroll
        for (int i = 0; i < TM; i++) {
            int gm = bm + trow * TM + i;
            #pragma unroll
            for (int j = 0; j < TN / 2; j++) {
                int gn = bn + tcol * TN + 2 * j;
                float lo, hi; unpack2(acc2[i][j], lo, hi);
                if (gn + 0 < N) Cz[(size_t)gm * N + gn + 0] = lo;
                if (gn + 1 < N) Cz[(size_t)gm * N + gn + 1] = hi;
            }
        }
    } else {
        #pragma unroll
        for (int i = 0; i < TM; i++) {
            int gm = bm + trow * TM + i;
            #pragma unroll
            for (int j = 0; j < TN / 2; j++) {
                int gn = bn + tcol * TN + 2 * j;
                float lo, hi; unpack2(acc2[i][j], lo, hi);
                if (gn + 0 < N) C[(size_t)gm * N + gn + 0] = sigmoidf_(lo + bias[gn + 0]);
                if (gn + 1 < N) C[(size_t)gm * N + gn + 1] = sigmoidf_(hi + bias[gn + 1]);
            }
        }
    }
}

// ---------------------------------------------------------------------------
// Kernel 3: encoder epilogue — sum split-K slabs + bias, sigmoid, store y_enc,
//           accumulate jac_reg = sum (y(1-y))^2 * rownorm2[f]
// ---------------------------------------------------------------------------
__global__ void enc_epilogue(const float* __restrict__ b_enc, float* __restrict__ jac_out) {
    int idx = blockIdx.x * blockDim.x + threadIdx.x;
    float part = 0.f;
    if (idx < BATCH * FEAT) {
        int f = idx % FEAT;
        float zsum = b_enc[f];
        #pragma unroll
        for (int s = 0; s < SPLITK; s++)
            zsum += g_preact[(size_t)s * BATCH * FEAT + idx];
        float y = sigmoidf_(zsum);
        g_yenc[idx] = y;
        float sder = y * (1.f - y);
        part = sder * sder * g_rownorm2[f];
    }
    // warp + block reduce, then atomic
    #pragma unroll
    for (int o = 16; o > 0; o >>= 1) part += __shfl_down_sync(0xffffffffu, part, o);
    __shared__ float wsum[8];
    int lane = threadIdx.x & 31, wid = threadIdx.x >> 5;
    if (lane == 0) wsum[wid] = part;
    __syncthreads();
    if (wid == 0) {
        float v = (lane < 8) ? wsum[lane] : 0.f;
        #pragma unroll
        for (int o = 4; o > 0; o >>= 1) v += __shfl_down_sync(0xffffffffu, v, o);
        if (lane == 0) atomicAdd(jac_out, v);
    }
}

// ---------------------------------------------------------------------------
extern "C" void kernel_launch(void* const* d_in, const int* in_sizes, int n_in,
                              void* d_out, int out_size) {
    const float* x     = (const float*)d_in[0];
    const float* W_enc = (const float*)d_in[1];
    const float* b_enc = (const float*)d_in[2];
    const float* W_dec = (const float*)d_in[3];
    const float* b_dec = (const float*)d_in[4];
    float* out = (float*)d_out;
    float* jac = out + (out_size - 1);   // [y_out | jac_reg] layout

    float *preact, *yenc;
    cudaGetSymbolAddress((void**)&preact, g_preact);
    cudaGetSymbolAddress((void**)&yenc,  g_yenc);

    // 1) W_enc row norms (+ jac zero-init)
    rownorm_kernel<<<FEAT, 256>>>(W_enc, jac);

    // 2) encoder GEMM, split-K=12 -> 12*2*12 = 288 CTAs
    {
        dim3 grid((FEAT + BN - 1) / BN, BATCH / BM, SPLITK);
        sgemm_nt<<<grid, NTHREADS>>>(x, W_enc, nullptr, preact,
                                     BATCH, FEAT, INSZ, INSZ / SPLITK, 0);
    }

    // 3) bias + sigmoid + jacobian reduction
    enc_epilogue<<<(BATCH * FEAT + 255) / 256, 256>>>(b_enc, jac);

    // 4) decoder GEMM with fused bias+sigmoid
    {
        dim3 grid((INSZ + BN - 1) / BN, BATCH / BM, 1);
        sgemm_nt<<<grid, NTHREADS>>>(yenc, W_dec, b_dec, out,
                                     BATCH, INSZ, FEAT, FEAT, 1);
    }
}

// round 8
// speedup vs baseline: 2.8736x; 2.8736x over previous
#include <cuda_runtime.h>
#include <cuda_bf16.h>
#include <cstdint>

// ---------------- problem constants ----------------
#define BATCH    256
#define FEAT     1500
#define FEAT_PAD 1536          // 48 * 32, padded K for decoder (zero-filled)
#define INSZ     28224
#define SPLITK   12
#define ENC_KBLK_TOTAL 882     // 28224 / 32
#define ENC_KBLK_PER_SPLIT 74  // 11*74 + 68 = 882
#define DEC_KBLK 48            // 1536 / 32

// ---------------- GEMM tile config -----------------
#define BM 128
#define BN 128
#define BK 32                  // K elements per chunk
#define NTH 256                // 8 warps: 2 (M) x 4 (N), warp tile 64x32

// smem: 4 tiles per stage (Ah, Al, Bh, Bl), each 128 rows x 32 bf16, row padded
// to 40 bf16 (80B) -> conflict-free ldmatrix, stage = 4*128*80 = 40960 B
#define ROWB   80              // bytes per smem row
#define TILE_B (128 * ROWB)    // 10240
#define STAGE_B (4 * TILE_B)   // 40960
#define SMEM_TOTAL (2 * STAGE_B)

#define OFF_AH 0
#define OFF_AL TILE_B
#define OFF_BH (2 * TILE_B)
#define OFF_BL (3 * TILE_B)

// ---------------- scratch ----------------
__device__ float g_preact[SPLITK * BATCH * FEAT];      // 18.4 MB
__device__ float g_yenc[BATCH * FEAT_PAD];             // zero-padded cols
__device__ float g_rownorm2[FEAT];

// ---------------- helpers ----------------
__device__ __forceinline__ uint32_t smem_u32(const void* p) {
    uint32_t a;
    asm("{ .reg .u64 t; cvta.to.shared.u64 t, %1; cvt.u32.u64 %0, t; }" : "=r"(a) : "l"(p));
    return a;
}
__device__ __forceinline__ float sigmoidf_(float z) { return 1.0f / (1.0f + __expf(-z)); }

// split float pair (x=k, y=k+1) into packed bf16x2 hi and lo words (k in low half)
__device__ __forceinline__ void split_pair(float x, float y, uint32_t& hw, uint32_t& lw) {
    uint32_t h;
    asm("cvt.rn.bf16x2.f32 %0, %1, %2;" : "=r"(h) : "f"(y), "f"(x));
    float hx = __uint_as_float(h << 16);
    float hy = __uint_as_float(h & 0xffff0000u);
    float lx = x - hx, ly = y - hy;
    asm("cvt.rn.bf16x2.f32 %0, %1, %2;" : "=r"(lw) : "f"(ly), "f"(lx));
    hw = h;
}

__device__ __forceinline__ void ldmx4(uint32_t r[4], uint32_t addr) {
    asm volatile("ldmatrix.sync.aligned.m8n8.x4.shared.b16 {%0,%1,%2,%3}, [%4];"
                 : "=r"(r[0]), "=r"(r[1]), "=r"(r[2]), "=r"(r[3]) : "r"(addr));
}
__device__ __forceinline__ void mma16816(float c[4], const uint32_t a[4], const uint32_t b[2]) {
    asm volatile(
        "mma.sync.aligned.m16n8k16.row.col.f32.bf16.bf16.f32 "
        "{%0,%1,%2,%3}, {%4,%5,%6,%7}, {%8,%9}, {%0,%1,%2,%3};"
        : "+f"(c[0]), "+f"(c[1]), "+f"(c[2]), "+f"(c[3])
        : "r"(a[0]), "r"(a[1]), "r"(a[2]), "r"(a[3]), "r"(b[0]), "r"(b[1]));
}

// ---------------------------------------------------------------------------
// split-bf16 HMMA GEMM: C[m,n] = sum_k A[m,k] * B[n,k]
//   A: [BM*gridY, lda] f32, all K valid (decoder A zero-padded to lda)
//   B: [N, ldb] f32, K valid in [0, kvalidB)
//   mode 0: raw f32 partial -> C + z*BATCH*ldc        (encoder split-K)
//   mode 1: sigmoid(acc + bias[n]) -> C               (decoder)
// ---------------------------------------------------------------------------
__global__ void __launch_bounds__(NTH, 1)
gemm_hmma(const float* __restrict__ A, const float* __restrict__ B,
          const float* __restrict__ bias, float* __restrict__ C,
          int N, int lda, int ldb, int kvalidB, int ldc,
          int kblk_per_split, int kblk_total, int mode)
{
    extern __shared__ char smem[];
    const uint32_t sb = smem_u32(smem);
    const int tid = threadIdx.x, wid = tid >> 5, lane = tid & 31;
    const int bm = blockIdx.y * BM;
    const int bn = blockIdx.x * BN;
    const int z  = blockIdx.z;
    const int kb0 = z * kblk_per_split;
    int nch = kblk_total - kb0;
    if (nch > kblk_per_split) nch = kblk_per_split;
    if (nch <= 0) return;

    const int wm = wid >> 2;        // 0..1  -> m offset wm*64
    const int wn = wid & 3;         // 0..3  -> n offset wn*32

    // loader mapping: 4 iterations, each thread loads one float4
    const int lrow = tid >> 3;          // 0..31 (+32 per it)
    const int lkg  = tid & 7;           // float4 index along K (0..7)

    float acc[4][4][4];
    #pragma unroll
    for (int i = 0; i < 4; i++)
        #pragma unroll
        for (int j = 0; j < 4; j++)
            #pragma unroll
            for (int q = 0; q < 4; q++) acc[i][j][q] = 0.f;

    float4 pa[4], pb[4];

    // ---- prefetch chunk 0 ----
    {
        const int kc = kb0 * BK + lkg * 4;
        #pragma unroll
        for (int it = 0; it < 4; it++) {
            int row = lrow + it * 32;
            pa[it] = *reinterpret_cast<const float4*>(A + (size_t)(bm + row) * lda + kc);
            int gn = bn + row;
            float4 v = make_float4(0.f, 0.f, 0.f, 0.f);
            if (gn < N && kc < kvalidB)
                v = *reinterpret_cast<const float4*>(B + (size_t)gn * ldb + kc);
            pb[it] = v;
        }
    }
    // ---- STS chunk 0 into buf 0 ----
    {
        char* st = smem;
        #pragma unroll
        for (int it = 0; it < 4; it++) {
            int row = lrow + it * 32;
            uint32_t off = (uint32_t)(row * ROWB + lkg * 8);
            uint32_t hw0, lw0, hw1, lw1;
            split_pair(pa[it].x, pa[it].y, hw0, lw0);
            split_pair(pa[it].z, pa[it].w, hw1, lw1);
            *reinterpret_cast<uint2*>(st + OFF_AH + off) = make_uint2(hw0, hw1);
            *reinterpret_cast<uint2*>(st + OFF_AL + off) = make_uint2(lw0, lw1);
            split_pair(pb[it].x, pb[it].y, hw0, lw0);
            split_pair(pb[it].z, pb[it].w, hw1, lw1);
            *reinterpret_cast<uint2*>(st + OFF_BH + off) = make_uint2(hw0, hw1);
            *reinterpret_cast<uint2*>(st + OFF_BL + off) = make_uint2(lw0, lw1);
        }
    }

    // ldmatrix base offsets for this thread
    const int lr = lane & 15;          // row within 16-row tile
    const int lc = lane >> 4;          // 0/1 -> +16B (k8..k15 half)

    for (int ci = 0; ci < nch; ci++) {
        __syncthreads();   // STS(ci) visible; all warps done computing ci-1

        // prefetch chunk ci+1
        if (ci + 1 < nch) {
            const int kc = (kb0 + ci + 1) * BK + lkg * 4;
            #pragma unroll
            for (int it = 0; it < 4; it++) {
                int row = lrow + it * 32;
                pa[it] = *reinterpret_cast<const float4*>(A + (size_t)(bm + row) * lda + kc);
                int gn = bn + row;
                float4 v = make_float4(0.f, 0.f, 0.f, 0.f);
                if (gn < N && kc < kvalidB)
                    v = *reinterpret_cast<const float4*>(B + (size_t)gn * ldb + kc);
                pb[it] = v;
            }
        }

        // ---- compute chunk ci from buf ci&1 ----
        const uint32_t stg = sb + (uint32_t)((ci & 1) * STAGE_B);
        #pragma unroll
        for (int ks = 0; ks < 2; ks++) {
            uint32_t ah[4][4], al[4][4], bh[4][2], bl[4][2];
            const uint32_t a_off = stg + (uint32_t)((wm * 64 + lr) * ROWB + lc * 16 + ks * 32);
            #pragma unroll
            for (int mi = 0; mi < 4; mi++) {
                ldmx4(ah[mi], a_off + OFF_AH + mi * 16 * ROWB);
                ldmx4(al[mi], a_off + OFF_AL + mi * 16 * ROWB);
            }
            const uint32_t b_off = stg + (uint32_t)((wn * 32 + lr) * ROWB + lc * 16 + ks * 32);
            #pragma unroll
            for (int bt = 0; bt < 2; bt++) {
                uint32_t t[4];
                ldmx4(t, b_off + OFF_BH + bt * 16 * ROWB);
                bh[bt * 2 + 0][0] = t[0]; bh[bt * 2 + 0][1] = t[2];
                bh[bt * 2 + 1][0] = t[1]; bh[bt * 2 + 1][1] = t[3];
                ldmx4(t, b_off + OFF_BL + bt * 16 * ROWB);
                bl[bt * 2 + 0][0] = t[0]; bl[bt * 2 + 0][1] = t[2];
                bl[bt * 2 + 1][0] = t[1]; bl[bt * 2 + 1][1] = t[3];
            }
            #pragma unroll
            for (int mi = 0; mi < 4; mi++)
                #pragma unroll
                for (int ni = 0; ni < 4; ni++) {
                    mma16816(acc[mi][ni], ah[mi], bh[ni]);
                    mma16816(acc[mi][ni], ah[mi], bl[ni]);
                    mma16816(acc[mi][ni], al[mi], bh[ni]);
                }
        }

        // ---- STS chunk ci+1 into buf (ci+1)&1 (other buffer; safe) ----
        if (ci + 1 < nch) {
            char* st = smem + ((ci + 1) & 1) * STAGE_B;
            #pragma unroll
            for (int it = 0; it < 4; it++) {
                int row = lrow + it * 32;
                uint32_t off = (uint32_t)(row * ROWB + lkg * 8);
                uint32_t hw0, lw0, hw1, lw1;
                split_pair(pa[it].x, pa[it].y, hw0, lw0);
                split_pair(pa[it].z, pa[it].w, hw1, lw1);
                *reinterpret_cast<uint2*>(st + OFF_AH + off) = make_uint2(hw0, hw1);
                *reinterpret_cast<uint2*>(st + OFF_AL + off) = make_uint2(lw0, lw1);
                split_pair(pb[it].x, pb[it].y, hw0, lw0);
                split_pair(pb[it].z, pb[it].w, hw1, lw1);
                *reinterpret_cast<uint2*>(st + OFF_BH + off) = make_uint2(hw0, hw1);
                *reinterpret_cast<uint2*>(st + OFF_BL + off) = make_uint2(lw0, lw1);
            }
        }
    }

    // ---- epilogue: write accumulators ----
    // c0,c1: row = lane/4,      col = (lane%4)*2 + {0,1}
    // c2,c3: row = lane/4 + 8,  col same
    const int er = lane >> 2, ec = (lane & 3) * 2;
    #pragma unroll
    for (int mi = 0; mi < 4; mi++) {
        #pragma unroll
        for (int ni = 0; ni < 4; ni++) {
            int m0 = bm + wm * 64 + mi * 16 + er;
            int n0 = bn + wn * 32 + ni * 8 + ec;
            if (mode == 0) {
                float* Cz = C + (size_t)z * BATCH * ldc;
                if (n0 + 1 < N) {
                    *reinterpret_cast<float2*>(Cz + (size_t)m0 * ldc + n0) =
                        make_float2(acc[mi][ni][0], acc[mi][ni][1]);
                    *reinterpret_cast<float2*>(Cz + (size_t)(m0 + 8) * ldc + n0) =
                        make_float2(acc[mi][ni][2], acc[mi][ni][3]);
                } else if (n0 < N) {
                    Cz[(size_t)m0 * ldc + n0] = acc[mi][ni][0];
                    Cz[(size_t)(m0 + 8) * ldc + n0] = acc[mi][ni][2];
                }
            } else {
                if (n0 + 1 < N) {
                    float b0 = bias[n0], b1 = bias[n0 + 1];
                    *reinterpret_cast<float2*>(C + (size_t)m0 * ldc + n0) =
                        make_float2(sigmoidf_(acc[mi][ni][0] + b0), sigmoidf_(acc[mi][ni][1] + b1));
                    *reinterpret_cast<float2*>(C + (size_t)(m0 + 8) * ldc + n0) =
                        make_float2(sigmoidf_(acc[mi][ni][2] + b0), sigmoidf_(acc[mi][ni][3] + b1));
                } else if (n0 < N) {
                    float b0 = bias[n0];
                    C[(size_t)m0 * ldc + n0] = sigmoidf_(acc[mi][ni][0] + b0);
                    C[(size_t)(m0 + 8) * ldc + n0] = sigmoidf_(acc[mi][ni][2] + b0);
                }
            }
        }
    }
}

// ---------------------------------------------------------------------------
// row_norm2[f] = sum_i W_enc[f,i]^2 ; zero-init jac accumulator
// ---------------------------------------------------------------------------
__global__ void rownorm_kernel(const float* __restrict__ W, float* __restrict__ jac_init) {
    int f = blockIdx.x;
    const float4* row = reinterpret_cast<const float4*>(W + (size_t)f * INSZ);
    float s = 0.f;
    for (int i = threadIdx.x; i < INSZ / 4; i += blockDim.x) {
        float4 v = row[i];
        s += v.x * v.x + v.y * v.y + v.z * v.z + v.w * v.w;
    }
    __shared__ float red[256];
    red[threadIdx.x] = s;
    __syncthreads();
    for (int o = 128; o > 0; o >>= 1) {
        if (threadIdx.x < o) red[threadIdx.x] += red[threadIdx.x + o];
        __syncthreads();
    }
    if (threadIdx.x == 0) g_rownorm2[f] = red[0];
    if (blockIdx.x == 0 && threadIdx.x == 0) *jac_init = 0.f;
}

// ---------------------------------------------------------------------------
// encoder epilogue: sum split-K partials + bias -> sigmoid -> y_enc (padded),
// accumulate jac_reg
// ---------------------------------------------------------------------------
__global__ void enc_epilogue(const float* __restrict__ b_enc, float* __restrict__ jac_out) {
    int idx = blockIdx.x * blockDim.x + threadIdx.x;
    float part = 0.f;
    if (idx < BATCH * FEAT_PAD) {
        int m = idx / FEAT_PAD, f = idx % FEAT_PAD;
        if (f < FEAT) {
            float zsum = b_enc[f];
            int base = m * FEAT + f;
            #pragma unroll
            for (int s = 0; s < SPLITK; s++)
                zsum += g_preact[(size_t)s * BATCH * FEAT + base];
            float y = sigmoidf_(zsum);
            g_yenc[idx] = y;
            float sd = y * (1.f - y);
            part = sd * sd * g_rownorm2[f];
        } else {
            g_yenc[idx] = 0.f;  // zero pad for decoder K
        }
    }
    #pragma unroll
    for (int o = 16; o > 0; o >>= 1) part += __shfl_down_sync(0xffffffffu, part, o);
    __shared__ float wsum[8];
    int lane = threadIdx.x & 31, wid = threadIdx.x >> 5;
    if (lane == 0) wsum[wid] = part;
    __syncthreads();
    if (wid == 0) {
        float v = (lane < 8) ? wsum[lane] : 0.f;
        #pragma unroll
        for (int o = 4; o > 0; o >>= 1) v += __shfl_down_sync(0xffffffffu, v, o);
        if (lane == 0) atomicAdd(jac_out, v);
    }
}

// ---------------------------------------------------------------------------
extern "C" void kernel_launch(void* const* d_in, const int* in_sizes, int n_in,
                              void* d_out, int out_size) {
    const float* x     = (const float*)d_in[0];
    const float* W_enc = (const float*)d_in[1];
    const float* b_enc = (const float*)d_in[2];
    const float* W_dec = (const float*)d_in[3];
    const float* b_dec = (const float*)d_in[4];
    float* out = (float*)d_out;
    float* jac = out + (out_size - 1);

    float *preact, *yenc;
    cudaGetSymbolAddress((void**)&preact, g_preact);
    cudaGetSymbolAddress((void**)&yenc,  g_yenc);

    cudaFuncSetAttribute(gemm_hmma, cudaFuncAttributeMaxDynamicSharedMemorySize, SMEM_TOTAL);

    // 1) W_enc row norms + jac zero-init
    rownorm_kernel<<<FEAT, 256>>>(W_enc, jac);

    // 2) encoder GEMM: [256,28224] @ [1500,28224]^T, split-K=12 -> 288 CTAs
    {
        dim3 grid((FEAT + BN - 1) / BN, BATCH / BM, SPLITK);   // (12, 2, 12)
        gemm_hmma<<<grid, NTH, SMEM_TOTAL>>>(
            x, W_enc, nullptr, preact,
            FEAT, INSZ, INSZ, INSZ, FEAT,
            ENC_KBLK_PER_SPLIT, ENC_KBLK_TOTAL, 0);
    }

    // 3) bias + sigmoid + jacobian reduction (+ y_enc zero pad)
    enc_epilogue<<<(BATCH * FEAT_PAD + 255) / 256, 256>>>(b_enc, jac);

    // 4) decoder GEMM: [256,1536pad] @ [28224,1500]^T, fused bias+sigmoid
    {
        dim3 grid((INSZ + BN - 1) / BN, BATCH / BM, 1);        // (221, 2, 1)
        gemm_hmma<<<grid, NTH, SMEM_TOTAL>>>(
            yenc, W_dec, b_dec, out,
            INSZ, FEAT_PAD, FEAT, FEAT, INSZ,
            DEC_KBLK, DEC_KBLK, 1);
    }
}

// round 9
// speedup vs baseline: 2.9520x; 1.0273x over previous
#include <cuda_runtime.h>
#include <cuda_bf16.h>
#include <cstdint>

// ---------------- problem constants ----------------
#define BATCH    256
#define FEAT     1500
#define FEAT_PAD 1536          // 96 * 16, padded K for decoder (zero-filled)
#define INSZ     28224
#define SPLITK   12
#define ENC_KBLK_TOTAL 1764    // 28224 / 16
#define ENC_KBLK_PER_SPLIT 147 // 12 * 147 = 1764 exactly
#define DEC_KBLK 96            // 1536 / 16

// ---------------- GEMM tile config -----------------
#define BM 128
#define BN 128
#define BK 16                  // K elements per chunk
#define NTH 256                // 8 warps: 2 (M) x 4 (N), warp tile 64x32

// smem: 4 tiles per stage (Ah, Al, Bh, Bl), each 128 rows x 16 bf16, row padded
// to 48B -> ldmatrix 8-row groups hit 8 distinct 16B segments (conflict-free)
#define ROWB   48
#define TILE_B (128 * ROWB)    // 6144
#define STAGE_B (4 * TILE_B)   // 24576
#define SMEM_TOTAL (2 * STAGE_B)  // 49152 -> 2 CTAs = 96KB/SM

#define OFF_AH 0
#define OFF_AL TILE_B
#define OFF_BH (2 * TILE_B)
#define OFF_BL (3 * TILE_B)

// ---------------- scratch ----------------
__device__ float g_preact[SPLITK * BATCH * FEAT];      // 18.4 MB
__device__ float g_yenc[BATCH * FEAT_PAD];             // zero-padded cols
__device__ float g_rownorm2[FEAT];

// ---------------- helpers ----------------
__device__ __forceinline__ uint32_t smem_u32(const void* p) {
    uint32_t a;
    asm("{ .reg .u64 t; cvta.to.shared.u64 t, %1; cvt.u32.u64 %0, t; }" : "=r"(a) : "l"(p));
    return a;
}
__device__ __forceinline__ float sigmoidf_(float z) { return 1.0f / (1.0f + __expf(-z)); }

// split float pair (x=k, y=k+1) into packed bf16x2 hi and lo words (k in low half)
__device__ __forceinline__ void split_pair(float x, float y, uint32_t& hw, uint32_t& lw) {
    uint32_t h;
    asm("cvt.rn.bf16x2.f32 %0, %1, %2;" : "=r"(h) : "f"(y), "f"(x));
    float hx = __uint_as_float(h << 16);
    float hy = __uint_as_float(h & 0xffff0000u);
    float lx = x - hx, ly = y - hy;
    asm("cvt.rn.bf16x2.f32 %0, %1, %2;" : "=r"(lw) : "f"(ly), "f"(lx));
    hw = h;
}

__device__ __forceinline__ void ldmx4(uint32_t r[4], uint32_t addr) {
    asm volatile("ldmatrix.sync.aligned.m8n8.x4.shared.b16 {%0,%1,%2,%3}, [%4];"
                 : "=r"(r[0]), "=r"(r[1]), "=r"(r[2]), "=r"(r[3]) : "r"(addr));
}
__device__ __forceinline__ void mma16816(float c[4], const uint32_t a[4], const uint32_t b0, const uint32_t b1) {
    asm volatile(
        "mma.sync.aligned.m16n8k16.row.col.f32.bf16.bf16.f32 "
        "{%0,%1,%2,%3}, {%4,%5,%6,%7}, {%8,%9}, {%0,%1,%2,%3};"
        : "+f"(c[0]), "+f"(c[1]), "+f"(c[2]), "+f"(c[3])
        : "r"(a[0]), "r"(a[1]), "r"(a[2]), "r"(a[3]), "r"(b0), "r"(b1));
}

// ---------------------------------------------------------------------------
// split-bf16 HMMA GEMM: C[m,n] = sum_k A[m,k] * B[n,k]
//   mode 0: raw f32 partial -> C + z*BATCH*ldc        (encoder split-K)
//   mode 1: sigmoid(acc + bias[n]) -> C               (decoder)
// ---------------------------------------------------------------------------
__global__ void __launch_bounds__(NTH, 2)
gemm_hmma(const float* __restrict__ A, const float* __restrict__ B,
          const float* __restrict__ bias, float* __restrict__ C,
          int N, int lda, int ldb, int kvalidB, int ldc,
          int kblk_per_split, int kblk_total, int mode)
{
    extern __shared__ char smem[];
    const uint32_t sb = smem_u32(smem);
    const int tid = threadIdx.x, wid = tid >> 5, lane = tid & 31;
    const int bm = blockIdx.y * BM;
    const int bn = blockIdx.x * BN;
    const int z  = blockIdx.z;
    const int kb0 = z * kblk_per_split;
    int nch = kblk_total - kb0;
    if (nch > kblk_per_split) nch = kblk_per_split;
    if (nch <= 0) return;

    const int wm = wid >> 2;        // 0..1  -> m offset wm*64
    const int wn = wid & 3;         // 0..3  -> n offset wn*32

    // loader: thread -> (row = tid>>2 (+64 per iter), quarter q = tid&3)
    const int lrow = tid >> 2;          // 0..63
    const int lq   = tid & 3;           // float4 index along K (0..3)

    float acc[4][4][4];
    #pragma unroll
    for (int i = 0; i < 4; i++)
        #pragma unroll
        for (int j = 0; j < 4; j++)
            #pragma unroll
            for (int q = 0; q < 4; q++) acc[i][j][q] = 0.f;

    float4 pa[2], pb[2];

    // ---- prefetch chunk 0 ----
    {
        const int kc = kb0 * BK + lq * 4;
        #pragma unroll
        for (int it = 0; it < 2; it++) {
            int row = lrow + it * 64;
            pa[it] = *reinterpret_cast<const float4*>(A + (size_t)(bm + row) * lda + kc);
            int gn = bn + row;
            float4 v = make_float4(0.f, 0.f, 0.f, 0.f);
            if (gn < N && kc < kvalidB)
                v = *reinterpret_cast<const float4*>(B + (size_t)gn * ldb + kc);
            pb[it] = v;
        }
    }
    // ---- STS chunk 0 into buf 0 ----
    {
        char* st = smem;
        #pragma unroll
        for (int it = 0; it < 2; it++) {
            int row = lrow + it * 64;
            uint32_t off = (uint32_t)(row * ROWB + lq * 8);
            uint32_t hw0, lw0, hw1, lw1;
            split_pair(pa[it].x, pa[it].y, hw0, lw0);
            split_pair(pa[it].z, pa[it].w, hw1, lw1);
            *reinterpret_cast<uint2*>(st + OFF_AH + off) = make_uint2(hw0, hw1);
            *reinterpret_cast<uint2*>(st + OFF_AL + off) = make_uint2(lw0, lw1);
            split_pair(pb[it].x, pb[it].y, hw0, lw0);
            split_pair(pb[it].z, pb[it].w, hw1, lw1);
            *reinterpret_cast<uint2*>(st + OFF_BH + off) = make_uint2(hw0, hw1);
            *reinterpret_cast<uint2*>(st + OFF_BL + off) = make_uint2(lw0, lw1);
        }
    }

    const int lr = lane & 15;          // row within 16-row tile
    const int lc = lane >> 4;          // 0/1 -> +16B (k8..k15 half)

    for (int ci = 0; ci < nch; ci++) {
        __syncthreads();   // STS(ci) visible; compute(ci-1) done

        // prefetch chunk ci+1 (held in regs during compute)
        if (ci + 1 < nch) {
            const int kc = (kb0 + ci + 1) * BK + lq * 4;
            #pragma unroll
            for (int it = 0; it < 2; it++) {
                int row = lrow + it * 64;
                pa[it] = *reinterpret_cast<const float4*>(A + (size_t)(bm + row) * lda + kc);
                int gn = bn + row;
                float4 v = make_float4(0.f, 0.f, 0.f, 0.f);
                if (gn < N && kc < kvalidB)
                    v = *reinterpret_cast<const float4*>(B + (size_t)gn * ldb + kc);
                pb[it] = v;
            }
        }

        // ---- compute chunk ci from buf ci&1 ----
        const uint32_t stg = sb + (uint32_t)((ci & 1) * STAGE_B);
        {
            // persistent B fragments: n-tile of 32 -> 2 ldmx4 each for hi/lo
            uint32_t bh[4][2], bl[4][2];
            const uint32_t b_off = stg + (uint32_t)((wn * 32 + lr) * ROWB + lc * 16);
            #pragma unroll
            for (int bt = 0; bt < 2; bt++) {
                uint32_t t[4];
                ldmx4(t, b_off + OFF_BH + bt * 16 * ROWB);
                bh[bt * 2 + 0][0] = t[0]; bh[bt * 2 + 0][1] = t[2];
                bh[bt * 2 + 1][0] = t[1]; bh[bt * 2 + 1][1] = t[3];
                ldmx4(t, b_off + OFF_BL + bt * 16 * ROWB);
                bl[bt * 2 + 0][0] = t[0]; bl[bt * 2 + 0][1] = t[2];
                bl[bt * 2 + 1][0] = t[1]; bl[bt * 2 + 1][1] = t[3];
            }
            const uint32_t a_off = stg + (uint32_t)((wm * 64 + lr) * ROWB + lc * 16);
            #pragma unroll
            for (int mi = 0; mi < 4; mi++) {
                uint32_t ah[4], al[4];
                ldmx4(ah, a_off + OFF_AH + mi * 16 * ROWB);
                ldmx4(al, a_off + OFF_AL + mi * 16 * ROWB);
                #pragma unroll
                for (int ni = 0; ni < 4; ni++)
                    mma16816(acc[mi][ni], ah, bh[ni][0], bh[ni][1]);
                #pragma unroll
                for (int ni = 0; ni < 4; ni++)
                    mma16816(acc[mi][ni], al, bh[ni][0], bh[ni][1]);
                #pragma unroll
                for (int ni = 0; ni < 4; ni++)
                    mma16816(acc[mi][ni], ah, bl[ni][0], bl[ni][1]);
            }
        }

        // ---- STS chunk ci+1 into other buffer ----
        if (ci + 1 < nch) {
            char* st = smem + ((ci + 1) & 1) * STAGE_B;
            #pragma unroll
            for (int it = 0; it < 2; it++) {
                int row = lrow + it * 64;
                uint32_t off = (uint32_t)(row * ROWB + lq * 8);
                uint32_t hw0, lw0, hw1, lw1;
                split_pair(pa[it].x, pa[it].y, hw0, lw0);
                split_pair(pa[it].z, pa[it].w, hw1, lw1);
                *reinterpret_cast<uint2*>(st + OFF_AH + off) = make_uint2(hw0, hw1);
                *reinterpret_cast<uint2*>(st + OFF_AL + off) = make_uint2(lw0, lw1);
                split_pair(pb[it].x, pb[it].y, hw0, lw0);
                split_pair(pb[it].z, pb[it].w, hw1, lw1);
                *reinterpret_cast<uint2*>(st + OFF_BH + off) = make_uint2(hw0, hw1);
                *reinterpret_cast<uint2*>(st + OFF_BL + off) = make_uint2(lw0, lw1);
            }
        }
    }

    // ---- epilogue ----
    const int er = lane >> 2, ec = (lane & 3) * 2;
    #pragma unroll
    for (int mi = 0; mi < 4; mi++) {
        #pragma unroll
        for (int ni = 0; ni < 4; ni++) {
            int m0 = bm + wm * 64 + mi * 16 + er;
            int n0 = bn + wn * 32 + ni * 8 + ec;
            if (mode == 0) {
                float* Cz = C + (size_t)z * BATCH * ldc;
                if (n0 + 1 < N) {
                    *reinterpret_cast<float2*>(Cz + (size_t)m0 * ldc + n0) =
                        make_float2(acc[mi][ni][0], acc[mi][ni][1]);
                    *reinterpret_cast<float2*>(Cz + (size_t)(m0 + 8) * ldc + n0) =
                        make_float2(acc[mi][ni][2], acc[mi][ni][3]);
                } else if (n0 < N) {
                    Cz[(size_t)m0 * ldc + n0] = acc[mi][ni][0];
                    Cz[(size_t)(m0 + 8) * ldc + n0] = acc[mi][ni][2];
                }
            } else {
                if (n0 + 1 < N) {
                    float b0 = bias[n0], b1 = bias[n0 + 1];
                    *reinterpret_cast<float2*>(C + (size_t)m0 * ldc + n0) =
                        make_float2(sigmoidf_(acc[mi][ni][0] + b0), sigmoidf_(acc[mi][ni][1] + b1));
                    *reinterpret_cast<float2*>(C + (size_t)(m0 + 8) * ldc + n0) =
                        make_float2(sigmoidf_(acc[mi][ni][2] + b0), sigmoidf_(acc[mi][ni][3] + b1));
                } else if (n0 < N) {
                    float b0 = bias[n0];
                    C[(size_t)m0 * ldc + n0] = sigmoidf_(acc[mi][ni][0] + b0);
                    C[(size_t)(m0 + 8) * ldc + n0] = sigmoidf_(acc[mi][ni][2] + b0);
                }
            }
        }
    }
}

// ---------------------------------------------------------------------------
// row_norm2[f] = sum_i W_enc[f,i]^2 ; zero-init jac accumulator
// ---------------------------------------------------------------------------
__global__ void rownorm_kernel(const float* __restrict__ W, float* __restrict__ jac_init) {
    int f = blockIdx.x;
    const float4* row = reinterpret_cast<const float4*>(W + (size_t)f * INSZ);
    float s = 0.f;
    for (int i = threadIdx.x; i < INSZ / 4; i += blockDim.x) {
        float4 v = row[i];
        s += v.x * v.x + v.y * v.y + v.z * v.z + v.w * v.w;
    }
    __shared__ float red[256];
    red[threadIdx.x] = s;
    __syncthreads();
    for (int o = 128; o > 0; o >>= 1) {
        if (threadIdx.x < o) red[threadIdx.x] += red[threadIdx.x + o];
        __syncthreads();
    }
    if (threadIdx.x == 0) g_rownorm2[f] = red[0];
    if (blockIdx.x == 0 && threadIdx.x == 0) *jac_init = 0.f;
}

// ---------------------------------------------------------------------------
// encoder epilogue: sum split-K partials + bias -> sigmoid -> y_enc (padded),
// accumulate jac_reg
// ---------------------------------------------------------------------------
__global__ void enc_epilogue(const float* __restrict__ b_enc, float* __restrict__ jac_out) {
    int idx = blockIdx.x * blockDim.x + threadIdx.x;
    float part = 0.f;
    if (idx < BATCH * FEAT_PAD) {
        int m = idx / FEAT_PAD, f = idx % FEAT_PAD;
        if (f < FEAT) {
            float zsum = b_enc[f];
            int base = m * FEAT + f;
            #pragma unroll
            for (int s = 0; s < SPLITK; s++)
                zsum += g_preact[(size_t)s * BATCH * FEAT + base];
            float y = sigmoidf_(zsum);
            g_yenc[idx] = y;
            float sd = y * (1.f - y);
            part = sd * sd * g_rownorm2[f];
        } else {
            g_yenc[idx] = 0.f;  // zero pad for decoder K
        }
    }
    #pragma unroll
    for (int o = 16; o > 0; o >>= 1) part += __shfl_down_sync(0xffffffffu, part, o);
    __shared__ float wsum[8];
    int lane = threadIdx.x & 31, wid = threadIdx.x >> 5;
    if (lane == 0) wsum[wid] = part;
    __syncthreads();
    if (wid == 0) {
        float v = (lane < 8) ? wsum[lane] : 0.f;
        #pragma unroll
        for (int o = 4; o > 0; o >>= 1) v += __shfl_down_sync(0xffffffffu, v, o);
        if (lane == 0) atomicAdd(jac_out, v);
    }
}

// ---------------------------------------------------------------------------
extern "C" void kernel_launch(void* const* d_in, const int* in_sizes, int n_in,
                              void* d_out, int out_size) {
    const float* x     = (const float*)d_in[0];
    const float* W_enc = (const float*)d_in[1];
    const float* b_enc = (const float*)d_in[2];
    const float* W_dec = (const float*)d_in[3];
    const float* b_dec = (const float*)d_in[4];
    float* out = (float*)d_out;
    float* jac = out + (out_size - 1);

    float *preact, *yenc;
    cudaGetSymbolAddress((void**)&preact, g_preact);
    cudaGetSymbolAddress((void**)&yenc,  g_yenc);

    cudaFuncSetAttribute(gemm_hmma, cudaFuncAttributeMaxDynamicSharedMemorySize, SMEM_TOTAL);

    // 1) W_enc row norms + jac zero-init
    rownorm_kernel<<<FEAT, 256>>>(W_enc, jac);

    // 2) encoder GEMM: [256,28224] @ [1500,28224]^T, split-K=12 -> 288 CTAs
    {
        dim3 grid((FEAT + BN - 1) / BN, BATCH / BM, SPLITK);   // (12, 2, 12)
        gemm_hmma<<<grid, NTH, SMEM_TOTAL>>>(
            x, W_enc, nullptr, preact,
            FEAT, INSZ, INSZ, INSZ, FEAT,
            ENC_KBLK_PER_SPLIT, ENC_KBLK_TOTAL, 0);
    }

    // 3) bias + sigmoid + jacobian reduction (+ y_enc zero pad)
    enc_epilogue<<<(BATCH * FEAT_PAD + 255) / 256, 256>>>(b_enc, jac);

    // 4) decoder GEMM: [256,1536pad] @ [28224,1500]^T, fused bias+sigmoid
    {
        dim3 grid((INSZ + BN - 1) / BN, BATCH / BM, 1);        // (221, 2, 1)
        gemm_hmma<<<grid, NTH, SMEM_TOTAL>>>(
            yenc, W_dec, b_dec, out,
            INSZ, FEAT_PAD, FEAT, FEAT, INSZ,
            DEC_KBLK, DEC_KBLK, 1);
    }
}